// round 3
// baseline (speedup 1.0000x reference)
#include <cuda_runtime.h>
#include <math.h>

#define NBT   32768     // B*T
#define HID   1024
#define G3    768       // 3*OUT
#define OUTD  256
#define TST   128
#define INF   128
#define BATCH 256

typedef unsigned long long ull;

// ---------------- device-global scratch (no allocations allowed) -----------
__device__ __align__(16) float d_e[NBT * HID];     // leaky(embed) activations
__device__ __align__(16) float d_gi[NBT * G3];     // hoisted input gates (hx GRU)
__device__ __align__(16) float d_gim[TST * G3];    // input gates (hm GRU)
__device__ float d_sum[HID];
__device__ float d_sumsq[HID];
__device__ __align__(16) float d_scale[HID];
__device__ __align__(16) float d_shift[HID];
__device__ __align__(16) float d_whhT[OUTD * G3];  // w_hh_x transposed [k][j]
__device__ __align__(16) float d_whhmT[OUTD * G3]; // w_hh_m transposed [k][j]
__device__ __align__(16) float d_hxf[BATCH * OUTD];
__device__ __align__(16) float d_hmf[OUTD];

// ---------------- packed f32x2 helpers -------------------------------------
__device__ __forceinline__ ull pk2(float lo, float hi) {
    ull r; asm("mov.b64 %0,{%1,%2};" : "=l"(r) : "f"(lo), "f"(hi)); return r;
}
__device__ __forceinline__ void fma2(ull& d, ull a, ull b) {
    asm("fma.rn.f32x2 %0,%1,%2,%3;" : "=l"(d) : "l"(a), "l"(b), "l"(d));
}
__device__ __forceinline__ float2 upk2(ull v) {
    float2 f; asm("mov.b64 {%0,%1},%2;" : "=f"(f.x), "=f"(f.y) : "l"(v)); return f;
}

// ---------------- k_zero ---------------------------------------------------
__global__ void k_zero() {
    int i = blockIdx.x * 256 + threadIdx.x;
    if (i < HID) { d_sum[i] = 0.0f; d_sumsq[i] = 0.0f; }
}

// ---------------- k_embed: e = leaky(x @ W_emb^T + b), fused BN stats ------
// M=32768 (grid.x=256), N=1024 (grid.y=8), K=128
__global__ void __launch_bounds__(256, 2)
k_embed(const float* __restrict__ x, const float* __restrict__ W,
        const float* __restrict__ bias) {
    __shared__ __align__(16) float As[16][132];
    __shared__ __align__(16) float Bs[16][132];
    const int m0 = blockIdx.x * 128, n0 = blockIdx.y * 128;
    const int tid = threadIdx.x, tx = tid & 15, ty = tid >> 4;
    const int q = tid & 3, r = tid >> 2;   // r in 0..63; second row r+64

    ull acc[8][4];
#pragma unroll
    for (int i = 0; i < 8; i++) { acc[i][0] = 0; acc[i][1] = 0; acc[i][2] = 0; acc[i][3] = 0; }

    for (int kt = 0; kt < INF / 16; kt++) {
        const int kk = kt * 16 + q * 4;
        float4 a0 = *(const float4*)&x[(m0 + r) * INF + kk];
        float4 a1 = *(const float4*)&x[(m0 + r + 64) * INF + kk];
        float4 b0 = *(const float4*)&W[(n0 + r) * INF + kk];
        float4 b1 = *(const float4*)&W[(n0 + r + 64) * INF + kk];
        As[q * 4 + 0][r] = a0.x; As[q * 4 + 1][r] = a0.y; As[q * 4 + 2][r] = a0.z; As[q * 4 + 3][r] = a0.w;
        As[q * 4 + 0][r + 64] = a1.x; As[q * 4 + 1][r + 64] = a1.y; As[q * 4 + 2][r + 64] = a1.z; As[q * 4 + 3][r + 64] = a1.w;
        Bs[q * 4 + 0][r] = b0.x; Bs[q * 4 + 1][r] = b0.y; Bs[q * 4 + 2][r] = b0.z; Bs[q * 4 + 3][r] = b0.w;
        Bs[q * 4 + 0][r + 64] = b1.x; Bs[q * 4 + 1][r + 64] = b1.y; Bs[q * 4 + 2][r + 64] = b1.z; Bs[q * 4 + 3][r + 64] = b1.w;
        __syncthreads();
#pragma unroll
        for (int k = 0; k < 16; k++) {
            float4 af0 = *(const float4*)&As[k][ty * 8];
            float4 af1 = *(const float4*)&As[k][ty * 8 + 4];
            ulonglong2 bp0 = *(const ulonglong2*)&Bs[k][tx * 8];
            ulonglong2 bp1 = *(const ulonglong2*)&Bs[k][tx * 8 + 4];
            float av[8] = {af0.x, af0.y, af0.z, af0.w, af1.x, af1.y, af1.z, af1.w};
#pragma unroll
            for (int i = 0; i < 8; i++) {
                ull ap = pk2(av[i], av[i]);
                fma2(acc[i][0], ap, bp0.x); fma2(acc[i][1], ap, bp0.y);
                fma2(acc[i][2], ap, bp1.x); fma2(acc[i][3], ap, bp1.y);
            }
        }
        __syncthreads();
    }

    // epilogue: bias + leaky + store + per-column stats
    float bv[8];
#pragma unroll
    for (int c = 0; c < 8; c++) bv[c] = bias[n0 + tx * 8 + c];
    float ssum[8], ssq[8];
#pragma unroll
    for (int c = 0; c < 8; c++) { ssum[c] = 0.0f; ssq[c] = 0.0f; }
#pragma unroll
    for (int i = 0; i < 8; i++) {
        const int m = m0 + ty * 8 + i;
        float* er = &d_e[(size_t)m * HID + n0 + tx * 8];
#pragma unroll
        for (int jj = 0; jj < 4; jj++) {
            float2 v = upk2(acc[i][jj]);
            const int c0 = jj * 2, c1 = jj * 2 + 1;
            float v0 = v.x + bv[c0]; v0 = (v0 >= 0.0f) ? v0 : 0.2f * v0;
            float v1 = v.y + bv[c1]; v1 = (v1 >= 0.0f) ? v1 : 0.2f * v1;
            er[c0] = v0; er[c1] = v1;
            ssum[c0] += v0; ssq[c0] += v0 * v0;
            ssum[c1] += v1; ssq[c1] += v1 * v1;
        }
    }
    __syncthreads();
#pragma unroll
    for (int c = 0; c < 8; c++) As[ty][tx * 8 + c] = ssum[c];
    __syncthreads();
    if (tid < 128) {
        float tot = 0.0f;
#pragma unroll
        for (int rr = 0; rr < 16; rr++) tot += As[rr][tid];
        atomicAdd(&d_sum[n0 + tid], tot);
    }
    __syncthreads();
#pragma unroll
    for (int c = 0; c < 8; c++) As[ty][tx * 8 + c] = ssq[c];
    __syncthreads();
    if (tid < 128) {
        float tot = 0.0f;
#pragma unroll
        for (int rr = 0; rr < 16; rr++) tot += As[rr][tid];
        atomicAdd(&d_sumsq[n0 + tid], tot);
    }
}

// ---------------- k_finalize: BN affine fold -------------------------------
__global__ void k_finalize(const float* __restrict__ gamma,
                           const float* __restrict__ beta) {
    const int h = threadIdx.x;  // 1024 threads, 1 block
    float mean = d_sum[h] * (1.0f / 32768.0f);
    float var = d_sumsq[h] * (1.0f / 32768.0f) - mean * mean;
    var = var > 0.0f ? var : 0.0f;
    float sc = gamma[h] * rsqrtf(var + 1e-5f);
    d_scale[h] = sc;
    d_shift[h] = beta[h] - mean * sc;
}

// ---------------- k_trans: transpose both hidden-weight matrices -----------
__global__ void k_trans(const float* __restrict__ wx, const float* __restrict__ wm) {
    const int idx = blockIdx.x * 256 + threadIdx.x;  // G3*OUTD = 196608
    if (idx < G3 * OUTD) {
        const int j = idx / OUTD, k = idx % OUTD;
        d_whhT[k * G3 + j] = wx[idx];
        d_whhmT[k * G3 + j] = wm[idx];
    }
}

// ---------------- k_gim: gim[t][j] = mem[t]·w_ih_m[j] + b_ih_m[j] ----------
__global__ void k_gim(const float* __restrict__ mem, const float* __restrict__ wim,
                      const float* __restrict__ bim) {
    const int t = blockIdx.x, j = threadIdx.x;  // 128 x 768
    const float4* m4 = (const float4*)(mem + t * HID);
    const float4* w4 = (const float4*)(wim + (size_t)j * HID);
    float acc = bim[j];
#pragma unroll 4
    for (int k = 0; k < HID / 4; k++) {
        float4 a = m4[k], b = w4[k];
        acc = fmaf(a.x, b.x, fmaf(a.y, b.y, fmaf(a.z, b.z, fmaf(a.w, b.w, acc))));
    }
    d_gim[t * G3 + j] = acc;
}

// ---------------- k_gemm2: gi = BN(e) @ w_ih_x^T + b_ih_x ------------------
// M=32768 (grid.x=256), N=768 (grid.y=6), K=1024. BN affine folded into A load.
__global__ void __launch_bounds__(256, 2)
k_gemm2(const float* __restrict__ Wi, const float* __restrict__ bias) {
    __shared__ __align__(16) float As[16][132];
    __shared__ __align__(16) float Bs[16][132];
    const int m0 = blockIdx.x * 128, n0 = blockIdx.y * 128;
    const int tid = threadIdx.x, tx = tid & 15, ty = tid >> 4;
    const int q = tid & 3, r = tid >> 2;

    ull acc[8][4];
#pragma unroll
    for (int i = 0; i < 8; i++) { acc[i][0] = 0; acc[i][1] = 0; acc[i][2] = 0; acc[i][3] = 0; }

    for (int kt = 0; kt < HID / 16; kt++) {
        const int kk = kt * 16 + q * 4;
        float4 sc = *(const float4*)&d_scale[kk];
        float4 sh = *(const float4*)&d_shift[kk];
        float4 e0 = *(const float4*)&d_e[(size_t)(m0 + r) * HID + kk];
        float4 e1 = *(const float4*)&d_e[(size_t)(m0 + r + 64) * HID + kk];
        float4 b0 = *(const float4*)&Wi[(size_t)(n0 + r) * HID + kk];
        float4 b1 = *(const float4*)&Wi[(size_t)(n0 + r + 64) * HID + kk];
        As[q * 4 + 0][r] = fmaf(e0.x, sc.x, sh.x); As[q * 4 + 1][r] = fmaf(e0.y, sc.y, sh.y);
        As[q * 4 + 2][r] = fmaf(e0.z, sc.z, sh.z); As[q * 4 + 3][r] = fmaf(e0.w, sc.w, sh.w);
        As[q * 4 + 0][r + 64] = fmaf(e1.x, sc.x, sh.x); As[q * 4 + 1][r + 64] = fmaf(e1.y, sc.y, sh.y);
        As[q * 4 + 2][r + 64] = fmaf(e1.z, sc.z, sh.z); As[q * 4 + 3][r + 64] = fmaf(e1.w, sc.w, sh.w);
        Bs[q * 4 + 0][r] = b0.x; Bs[q * 4 + 1][r] = b0.y; Bs[q * 4 + 2][r] = b0.z; Bs[q * 4 + 3][r] = b0.w;
        Bs[q * 4 + 0][r + 64] = b1.x; Bs[q * 4 + 1][r + 64] = b1.y; Bs[q * 4 + 2][r + 64] = b1.z; Bs[q * 4 + 3][r + 64] = b1.w;
        __syncthreads();
#pragma unroll
        for (int k = 0; k < 16; k++) {
            float4 af0 = *(const float4*)&As[k][ty * 8];
            float4 af1 = *(const float4*)&As[k][ty * 8 + 4];
            ulonglong2 bp0 = *(const ulonglong2*)&Bs[k][tx * 8];
            ulonglong2 bp1 = *(const ulonglong2*)&Bs[k][tx * 8 + 4];
            float av[8] = {af0.x, af0.y, af0.z, af0.w, af1.x, af1.y, af1.z, af1.w};
#pragma unroll
            for (int i = 0; i < 8; i++) {
                ull ap = pk2(av[i], av[i]);
                fma2(acc[i][0], ap, bp0.x); fma2(acc[i][1], ap, bp0.y);
                fma2(acc[i][2], ap, bp1.x); fma2(acc[i][3], ap, bp1.y);
            }
        }
        __syncthreads();
    }

    float bv[8];
#pragma unroll
    for (int c = 0; c < 8; c++) bv[c] = bias[n0 + tx * 8 + c];
#pragma unroll
    for (int i = 0; i < 8; i++) {
        const int m = m0 + ty * 8 + i;
        float* gr = &d_gi[(size_t)m * G3 + n0 + tx * 8];
#pragma unroll
        for (int jj = 0; jj < 4; jj++) {
            float2 v = upk2(acc[i][jj]);
            gr[jj * 2] = v.x + bv[jj * 2];
            gr[jj * 2 + 1] = v.y + bv[jj * 2 + 1];
        }
    }
}

// ---------------- k_scan: persistent GRU recurrences -----------------------
// CTAs 0..63: hx for 4 batch rows each (independent per row -> no grid sync).
// CTA 64: the batch-invariant hm chain.
__global__ void __launch_bounds__(384, 1)
k_scan(const float* __restrict__ bhhx, const float* __restrict__ bhhm) {
    __shared__ ull hxd[4][OUTD];      // duplicated-pair hidden state (h,h)
    __shared__ float gh[4][G3];
    const int tid = threadIdx.x;
    const int j0 = 2 * tid;           // this thread's two gate columns

    if (blockIdx.x < 64) {
        const int bb = blockIdx.x * 4;
        for (int i = tid; i < 4 * OUTD; i += 384) ((ull*)hxd)[i] = 0ull;
        const ull bh = *(const ull*)&bhhx[j0];
        __syncthreads();
        for (int t = 0; t < TST; t++) {
            ull a0 = bh, a1 = bh, a2 = bh, a3 = bh;
#pragma unroll 4
            for (int k = 0; k < OUTD; k++) {
                ull w = *(const ull*)&d_whhT[k * G3 + j0];
                fma2(a0, hxd[0][k], w); fma2(a1, hxd[1][k], w);
                fma2(a2, hxd[2][k], w); fma2(a3, hxd[3][k], w);
            }
            *(ull*)&gh[0][j0] = a0; *(ull*)&gh[1][j0] = a1;
            *(ull*)&gh[2][j0] = a2; *(ull*)&gh[3][j0] = a3;
            __syncthreads();
            if (tid < OUTD) {
#pragma unroll
                for (int b = 0; b < 4; b++) {
                    const float* gi = &d_gi[((size_t)(bb + b) * TST + t) * G3];
                    float hold = upk2(hxd[b][tid]).x;
                    float rr = 1.0f / (1.0f + expf(-(gi[tid] + gh[b][tid])));
                    float zz = 1.0f / (1.0f + expf(-(gi[OUTD + tid] + gh[b][OUTD + tid])));
                    float nn = tanhf(gi[2 * OUTD + tid] + rr * gh[b][2 * OUTD + tid]);
                    float hnew = (1.0f - zz) * nn + zz * hold;
                    hxd[b][tid] = pk2(hnew, hnew);
                }
            }
            __syncthreads();
        }
        if (tid < OUTD) {
#pragma unroll
            for (int b = 0; b < 4; b++)
                d_hxf[(bb + b) * OUTD + tid] = upk2(hxd[b][tid]).x;
        }
    } else {
        for (int i = tid; i < OUTD; i += 384) hxd[0][i] = 0ull;
        const ull bh = *(const ull*)&bhhm[j0];
        __syncthreads();
        for (int t = 0; t < TST; t++) {
            ull a0 = bh;
#pragma unroll 4
            for (int k = 0; k < OUTD; k++) {
                ull w = *(const ull*)&d_whhmT[k * G3 + j0];
                fma2(a0, hxd[0][k], w);
            }
            *(ull*)&gh[0][j0] = a0;
            __syncthreads();
            if (tid < OUTD) {
                const float* gi = &d_gim[t * G3];
                float hold = upk2(hxd[0][tid]).x;
                float rr = 1.0f / (1.0f + expf(-(gi[tid] + gh[0][tid])));
                float zz = 1.0f / (1.0f + expf(-(gi[OUTD + tid] + gh[0][OUTD + tid])));
                float nn = tanhf(gi[2 * OUTD + tid] + rr * gh[0][2 * OUTD + tid]);
                float hnew = (1.0f - zz) * nn + zz * hold;
                hxd[0][tid] = pk2(hnew, hnew);
            }
            __syncthreads();
        }
        if (tid < OUTD) d_hmf[tid] = upk2(hxd[0][tid]).x;
    }
}

// ---------------- k_final: cosine gate + blend -----------------------------
__global__ void k_final(const float* __restrict__ Wsx, const float* __restrict__ bsx,
                        const float* __restrict__ Wsm, const float* __restrict__ bsm,
                        float* __restrict__ out) {
    const int b = blockIdx.x, lane = threadIdx.x;  // 256 blocks x 32 threads
    float hx[8], hm[8];
#pragma unroll
    for (int i = 0; i < 8; i++) {
        hx[i] = d_hxf[b * OUTD + lane * 8 + i];
        hm[i] = d_hmf[lane * 8 + i];
    }
    float qx[4], qm[4];
#pragma unroll
    for (int s = 0; s < 4; s++) {
        float ax = 0.0f, am = 0.0f;
#pragma unroll
        for (int i = 0; i < 8; i++) {
            ax = fmaf(hx[i], Wsx[s * OUTD + lane * 8 + i], ax);
            am = fmaf(hm[i], Wsm[s * OUTD + lane * 8 + i], am);
        }
        for (int off = 16; off; off >>= 1) {
            ax += __shfl_xor_sync(0xFFFFFFFFu, ax, off);
            am += __shfl_xor_sync(0xFFFFFFFFu, am, off);
        }
        qx[s] = ax + bsx[s];
        qm[s] = am + bsm[s];
    }
    float num = 0.0f, nx = 0.0f, nm = 0.0f;
#pragma unroll
    for (int s = 0; s < 4; s++) {
        num = fmaf(qx[s], qm[s], num);
        nx = fmaf(qx[s], qx[s], nx);
        nm = fmaf(qm[s], qm[s], nm);
    }
    float den = fmaxf(sqrtf(nx), 1e-8f) * fmaxf(sqrtf(nm), 1e-8f);
    float g = 1.0f / (1.0f + expf(-num / den));
#pragma unroll
    for (int i = 0; i < 8; i++)
        out[b * OUTD + lane * 8 + i] = g * hx[i] + (1.0f - g) * hm[i];
}

// ---------------- launcher -------------------------------------------------
extern "C" void kernel_launch(void* const* d_in, const int* in_sizes, int n_in,
                              void* d_out, int out_size) {
    const float* x      = (const float*)d_in[0];
    const float* W_emb  = (const float*)d_in[1];
    const float* b_emb  = (const float*)d_in[2];
    const float* gamma  = (const float*)d_in[3];
    const float* beta   = (const float*)d_in[4];
    const float* memory = (const float*)d_in[5];
    const float* w_ih_x = (const float*)d_in[6];
    const float* w_hh_x = (const float*)d_in[7];
    const float* b_ih_x = (const float*)d_in[8];
    const float* b_hh_x = (const float*)d_in[9];
    const float* w_ih_m = (const float*)d_in[10];
    const float* w_hh_m = (const float*)d_in[11];
    const float* b_ih_m = (const float*)d_in[12];
    const float* b_hh_m = (const float*)d_in[13];
    const float* W_sx   = (const float*)d_in[14];
    const float* b_sx   = (const float*)d_in[15];
    const float* W_sm   = (const float*)d_in[16];
    const float* b_sm   = (const float*)d_in[17];
    float* out = (float*)d_out;

    k_zero<<<4, 256>>>();
    k_embed<<<dim3(256, 8), 256>>>(x, W_emb, b_emb);
    k_finalize<<<1, 1024>>>(gamma, beta);
    k_trans<<<768, 256>>>(w_hh_x, w_hh_m);
    k_gim<<<128, 768>>>(memory, w_ih_m, b_ih_m);
    k_gemm2<<<dim3(256, 6), 256>>>(w_ih_x, b_ih_x);
    k_scan<<<65, 384>>>(b_hh_x, b_hh_m);
    k_final<<<256, 32>>>(W_sx, b_sx, W_sm, b_sm, out);
}